// round 16
// baseline (speedup 1.0000x reference)
#include <cuda_runtime.h>
#include <cuda_fp16.h>
#include <cstdint>

#define N_NODES 100000
#define N_EDGES 1600000
#define D 128
#define NGRAPH 64
#define DOUT 16
#define LN_EPS 1e-5f
#define SCAN_B 1024
#define SCAN_NB ((N_NODES + SCAN_B - 1) / SCAN_B)   // 98

// ---------------- scratch (static device globals; no allocation) ----------------
__device__ __half g_Ah[N_NODES * D];     // GEMM output, dinv-prescaled, fp16
__device__ float  g_B[N_NODES * D];      // fp16 LN1 output lives here
__device__ int    g_cnti[N_NODES];
__device__ int    g_offs[N_NODES + 1];
__device__ int    g_cursor[N_NODES];
__device__ int    g_adj[N_EDGES];
__device__ int    g_bsum[SCAN_NB];
__device__ float  g_dinv[N_NODES];
__device__ float  g_pooled[NGRAPH * D];
__device__ float  g_gcnt[NGRAPH];

// ---------------- degree count ----------------
__global__ void k_count(const int* __restrict__ dst) {
    int i = blockIdx.x * blockDim.x + threadIdx.x;
    if (i < N_EDGES) atomicAdd(&g_cnti[dst[i]], 1);
}

// ---------------- prefix scan (dinv fused into scan1) ----------------
__global__ void k_scan1() {
    __shared__ int sh[SCAN_B];
    int i = blockIdx.x * SCAN_B + threadIdx.x;
    int v = (i < N_NODES) ? g_cnti[i] : 0;
    if (i < N_NODES) g_dinv[i] = rsqrtf((float)(v + 1));   // +1 self-loop
    sh[threadIdx.x] = v;
    __syncthreads();
#pragma unroll
    for (int o = 1; o < SCAN_B; o <<= 1) {
        int t = (threadIdx.x >= o) ? sh[threadIdx.x - o] : 0;
        __syncthreads();
        sh[threadIdx.x] += t;
        __syncthreads();
    }
    if (i < N_NODES) g_offs[i + 1] = sh[threadIdx.x];
    if (threadIdx.x == SCAN_B - 1) g_bsum[blockIdx.x] = sh[SCAN_B - 1];
}

__global__ void k_scan2() {
    __shared__ int sh[128];
    int t = threadIdx.x;
    int v = (t < SCAN_NB) ? g_bsum[t] : 0;
    sh[t] = v;
    __syncthreads();
#pragma unroll
    for (int o = 1; o < 128; o <<= 1) {
        int u = (t >= o) ? sh[t - o] : 0;
        __syncthreads();
        sh[t] += u;
        __syncthreads();
    }
    if (t < SCAN_NB) g_bsum[t] = sh[t] - v;   // exclusive
}

__global__ void k_scan3() {
    int i = blockIdx.x * SCAN_B + threadIdx.x;
    if (i < N_NODES) {
        int incl = g_offs[i + 1] + g_bsum[blockIdx.x];
        g_offs[i + 1] = incl;
        if (i + 1 < N_NODES) g_cursor[i + 1] = incl;
    }
    if (i == 0) { g_offs[0] = 0; g_cursor[0] = 0; }
}

__global__ void k_fill(const int* __restrict__ src, const int* __restrict__ dst) {
    int e = blockIdx.x * blockDim.x + threadIdx.x;
    if (e < N_EDGES) {
        int d = dst[e];
        int pos = atomicAdd(&g_cursor[d], 1);
        g_adj[pos] = src[e];
    }
}

// zero cnti/pooled/gcnt for the rest of this launch + the next call.
__global__ void k_zero() {
    int i = blockIdx.x * blockDim.x + threadIdx.x;
    if (i < N_NODES) g_cnti[i] = 0;
    if (i < NGRAPH * D) g_pooled[i] = 0.0f;
    if (i < NGRAPH) g_gcnt[i] = 0.0f;
}

// ---------------- TF32 tensor-core GEMM ----------------
#define AS_STRIDE 36
#define WS_STRIDE 132

__device__ __forceinline__ uint32_t f2tf32(float f) {
    uint32_t u;
    asm("cvt.rna.tf32.f32 %0, %1;" : "=r"(u) : "f"(f));
    return u;
}

// GEMM1: fp32 A; epilogue computes dinv from cnti.
__global__ void __launch_bounds__(256) k_gemm(const float* __restrict__ A,
                                              const float* __restrict__ W,
                                              __half* __restrict__ Ch) {
    __shared__ uint32_t As[128 * AS_STRIDE];
    __shared__ uint32_t Ws[32 * WS_STRIDE];
    int tid = threadIdx.x;
    int lane = tid & 31;
    int w = tid >> 5;
    int warpM = (w >> 1) * 32;
    int warpN = (w & 1) * 64;
    int g = lane >> 2;
    int t = lane & 3;
    int rowBase = blockIdx.x * 128;

    float c[2][8][4];
#pragma unroll
    for (int mi = 0; mi < 2; mi++)
#pragma unroll
        for (int nt = 0; nt < 8; nt++)
#pragma unroll
            for (int q = 0; q < 4; q++) c[mi][nt][q] = 0.f;

    for (int k0 = 0; k0 < 128; k0 += 32) {
#pragma unroll
        for (int i = 0; i < 4; i++) {
            int idx = tid + i * 256;
            int r = idx >> 3;
            int c4 = idx & 7;
            int grow = rowBase + r;
            float4 v = make_float4(0.f, 0.f, 0.f, 0.f);
            if (grow < N_NODES)
                v = *reinterpret_cast<const float4*>(&A[grow * D + k0 + c4 * 4]);
            uint32_t* p = &As[r * AS_STRIDE + c4 * 4];
            p[0] = f2tf32(v.x); p[1] = f2tf32(v.y);
            p[2] = f2tf32(v.z); p[3] = f2tf32(v.w);
        }
#pragma unroll
        for (int i = 0; i < 4; i++) {
            int idx = tid + i * 256;
            int r = idx >> 5;
            int c4 = idx & 31;
            float4 v = *reinterpret_cast<const float4*>(&W[(k0 + r) * D + c4 * 4]);
            uint32_t* p = &Ws[r * WS_STRIDE + c4 * 4];
            p[0] = f2tf32(v.x); p[1] = f2tf32(v.y);
            p[2] = f2tf32(v.z); p[3] = f2tf32(v.w);
        }
        __syncthreads();

#pragma unroll
        for (int kk = 0; kk < 4; kk++) {
            int kb = kk * 8;
            uint32_t af[2][4];
#pragma unroll
            for (int mi = 0; mi < 2; mi++) {
                int r = warpM + mi * 16;
                af[mi][0] = As[(r + g)     * AS_STRIDE + kb + t];
                af[mi][1] = As[(r + g + 8) * AS_STRIDE + kb + t];
                af[mi][2] = As[(r + g)     * AS_STRIDE + kb + t + 4];
                af[mi][3] = As[(r + g + 8) * AS_STRIDE + kb + t + 4];
            }
#pragma unroll
            for (int nt = 0; nt < 8; nt++) {
                int nb = warpN + nt * 8;
                uint32_t b0 = Ws[(kb + t)     * WS_STRIDE + nb + g];
                uint32_t b1 = Ws[(kb + t + 4) * WS_STRIDE + nb + g];
#pragma unroll
                for (int mi = 0; mi < 2; mi++) {
                    asm volatile(
                        "mma.sync.aligned.m16n8k8.row.col.f32.tf32.tf32.f32 "
                        "{%0,%1,%2,%3}, {%4,%5,%6,%7}, {%8,%9}, {%0,%1,%2,%3};"
                        : "+f"(c[mi][nt][0]), "+f"(c[mi][nt][1]),
                          "+f"(c[mi][nt][2]), "+f"(c[mi][nt][3])
                        : "r"(af[mi][0]), "r"(af[mi][1]), "r"(af[mi][2]), "r"(af[mi][3]),
                          "r"(b0), "r"(b1));
                }
            }
        }
        __syncthreads();
    }

    __half2* Ch2 = reinterpret_cast<__half2*>(Ch);
#pragma unroll
    for (int mi = 0; mi < 2; mi++) {
        int r0 = rowBase + warpM + mi * 16 + g;
        int r1 = r0 + 8;
        float d0 = (r0 < N_NODES) ? rsqrtf((float)(__ldg(&g_cnti[r0]) + 1)) : 0.f;
        float d1 = (r1 < N_NODES) ? rsqrtf((float)(__ldg(&g_cnti[r1]) + 1)) : 0.f;
#pragma unroll
        for (int nt = 0; nt < 8; nt++) {
            int colBase = warpN + nt * 8 + t * 2;
            if (r0 < N_NODES)
                Ch2[r0 * 64 + (colBase >> 1)] =
                    __floats2half2_rn(c[mi][nt][0] * d0, c[mi][nt][1] * d0);
            if (r1 < N_NODES)
                Ch2[r1 * 64 + (colBase >> 1)] =
                    __floats2half2_rn(c[mi][nt][2] * d1, c[mi][nt][3] * d1);
        }
    }
}

// GEMM2: fp16 A; epilogue uses g_dinv (ready after join).
__global__ void __launch_bounds__(256) k_gemmh(const __half* __restrict__ A,
                                               const float* __restrict__ W,
                                               __half* __restrict__ Ch) {
    __shared__ uint32_t As[128 * AS_STRIDE];
    __shared__ uint32_t Ws[32 * WS_STRIDE];
    int tid = threadIdx.x;
    int lane = tid & 31;
    int w = tid >> 5;
    int warpM = (w >> 1) * 32;
    int warpN = (w & 1) * 64;
    int g = lane >> 2;
    int t = lane & 3;
    int rowBase = blockIdx.x * 128;

    float c[2][8][4];
#pragma unroll
    for (int mi = 0; mi < 2; mi++)
#pragma unroll
        for (int nt = 0; nt < 8; nt++)
#pragma unroll
            for (int q = 0; q < 4; q++) c[mi][nt][q] = 0.f;

    for (int k0 = 0; k0 < 128; k0 += 32) {
#pragma unroll
        for (int i = 0; i < 4; i++) {
            int idx = tid + i * 256;
            int r = idx >> 3;
            int c4 = idx & 7;
            int grow = rowBase + r;
            uint2 v = make_uint2(0u, 0u);
            if (grow < N_NODES)
                v = *reinterpret_cast<const uint2*>(&A[grow * D + k0 + c4 * 4]);
            float2 f0 = __half22float2(*reinterpret_cast<__half2*>(&v.x));
            float2 f1 = __half22float2(*reinterpret_cast<__half2*>(&v.y));
            uint32_t* p = &As[r * AS_STRIDE + c4 * 4];
            p[0] = f2tf32(f0.x); p[1] = f2tf32(f0.y);
            p[2] = f2tf32(f1.x); p[3] = f2tf32(f1.y);
        }
#pragma unroll
        for (int i = 0; i < 4; i++) {
            int idx = tid + i * 256;
            int r = idx >> 5;
            int c4 = idx & 31;
            float4 v = *reinterpret_cast<const float4*>(&W[(k0 + r) * D + c4 * 4]);
            uint32_t* p = &Ws[r * WS_STRIDE + c4 * 4];
            p[0] = f2tf32(v.x); p[1] = f2tf32(v.y);
            p[2] = f2tf32(v.z); p[3] = f2tf32(v.w);
        }
        __syncthreads();

#pragma unroll
        for (int kk = 0; kk < 4; kk++) {
            int kb = kk * 8;
            uint32_t af[2][4];
#pragma unroll
            for (int mi = 0; mi < 2; mi++) {
                int r = warpM + mi * 16;
                af[mi][0] = As[(r + g)     * AS_STRIDE + kb + t];
                af[mi][1] = As[(r + g + 8) * AS_STRIDE + kb + t];
                af[mi][2] = As[(r + g)     * AS_STRIDE + kb + t + 4];
                af[mi][3] = As[(r + g + 8) * AS_STRIDE + kb + t + 4];
            }
#pragma unroll
            for (int nt = 0; nt < 8; nt++) {
                int nb = warpN + nt * 8;
                uint32_t b0 = Ws[(kb + t)     * WS_STRIDE + nb + g];
                uint32_t b1 = Ws[(kb + t + 4) * WS_STRIDE + nb + g];
#pragma unroll
                for (int mi = 0; mi < 2; mi++) {
                    asm volatile(
                        "mma.sync.aligned.m16n8k8.row.col.f32.tf32.tf32.f32 "
                        "{%0,%1,%2,%3}, {%4,%5,%6,%7}, {%8,%9}, {%0,%1,%2,%3};"
                        : "+f"(c[mi][nt][0]), "+f"(c[mi][nt][1]),
                          "+f"(c[mi][nt][2]), "+f"(c[mi][nt][3])
                        : "r"(af[mi][0]), "r"(af[mi][1]), "r"(af[mi][2]), "r"(af[mi][3]),
                          "r"(b0), "r"(b1));
                }
            }
        }
        __syncthreads();
    }

    __half2* Ch2 = reinterpret_cast<__half2*>(Ch);
#pragma unroll
    for (int mi = 0; mi < 2; mi++) {
        int r0 = rowBase + warpM + mi * 16 + g;
        int r1 = r0 + 8;
        float d0 = (r0 < N_NODES) ? __ldg(&g_dinv[r0]) : 0.f;
        float d1 = (r1 < N_NODES) ? __ldg(&g_dinv[r1]) : 0.f;
#pragma unroll
        for (int nt = 0; nt < 8; nt++) {
            int colBase = warpN + nt * 8 + t * 2;
            if (r0 < N_NODES)
                Ch2[r0 * 64 + (colBase >> 1)] =
                    __floats2half2_rn(c[mi][nt][0] * d0, c[mi][nt][1] * d0);
            if (r1 < N_NODES)
                Ch2[r1 * 64 + (colBase >> 1)] =
                    __floats2half2_rn(c[mi][nt][2] * d1, c[mi][nt][3] * d1);
        }
    }
}

// ---------------- gather body: 1 node/warp, 2 rows per LDG.128 ----------------
// Lanes 0-15 handle neighbor jj, lanes 16-31 neighbor jj+1 (same trip count ->
// warp stays converged; full shuffle masks are valid). Each lane loads uint4
// (8 halfs = features [8*hlane, 8*hlane+8)). Final shfl_xor(16) folds halves.
__device__ __forceinline__ void h16_to_f8(uint4 u, float* f) {
    float2 t;
    t = __half22float2(*reinterpret_cast<__half2*>(&u.x)); f[0] = t.x; f[1] = t.y;
    t = __half22float2(*reinterpret_cast<__half2*>(&u.y)); f[2] = t.x; f[3] = t.y;
    t = __half22float2(*reinterpret_cast<__half2*>(&u.z)); f[4] = t.x; f[5] = t.y;
    t = __half22float2(*reinterpret_cast<__half2*>(&u.w)); f[6] = t.x; f[7] = t.y;
}

__device__ __forceinline__ void gather_ln_row8(const __half* __restrict__ h,
                                               const float* __restrict__ bias,
                                               const float* __restrict__ lng,
                                               const float* __restrict__ lnb,
                                               int node, int lane, float* outv) {
    int hlane = lane & 15;
    int hsel = lane >> 4;                       // 0 = even neighbor, 1 = odd
    float di = g_dinv[node];
    const uint4* __restrict__ hu4 = reinterpret_cast<const uint4*>(h);  // 16/row

    float a0[8], a1[8];
    {
        uint4 su = make_uint4(0u, 0u, 0u, 0u);
        if (hsel == 0) su = __ldg(&hu4[node * 16 + hlane]);   // self once
        h16_to_f8(su, a0);
#pragma unroll
        for (int q = 0; q < 8; q++) a1[q] = 0.f;
    }

    int beg = __ldg(&g_offs[node]);
    int end = __ldg(&g_offs[node + 1]);
    for (int j0 = beg; j0 < end; j0 += 32) {
        int rem = end - j0;
        int n = rem < 32 ? rem : 32;
        int myidx = 0;
        if (lane < n) myidx = __ldg(&g_adj[j0 + lane]);
        int jj = 0;
#pragma unroll 2
        for (; jj + 4 <= n; jj += 4) {
            int sA = __shfl_sync(0xFFFFFFFFu, myidx, jj + hsel);
            int sB = __shfl_sync(0xFFFFFFFFu, myidx, jj + 2 + hsel);
            uint4 uA = __ldg(&hu4[sA * 16 + hlane]);
            uint4 uB = __ldg(&hu4[sB * 16 + hlane]);
            float fA[8], fB[8];
            h16_to_f8(uA, fA);
            h16_to_f8(uB, fB);
#pragma unroll
            for (int q = 0; q < 8; q++) { a0[q] += fA[q]; a1[q] += fB[q]; }
        }
        if (jj + 2 <= n) {
            int sA = __shfl_sync(0xFFFFFFFFu, myidx, jj + hsel);
            uint4 uA = __ldg(&hu4[sA * 16 + hlane]);
            float fA[8];
            h16_to_f8(uA, fA);
#pragma unroll
            for (int q = 0; q < 8; q++) a0[q] += fA[q];
            jj += 2;
        }
        if (jj < n) {
            int sT = __shfl_sync(0xFFFFFFFFu, myidx, jj);
            uint4 uT = make_uint4(0u, 0u, 0u, 0u);
            if (hsel == 0) uT = __ldg(&hu4[sT * 16 + hlane]);  // odd tail: once
            float fT[8];
            h16_to_f8(uT, fT);
#pragma unroll
            for (int q = 0; q < 8; q++) a1[q] += fT[q];
        }
    }

    // fold the two half-warp partial sums
    float acc[8];
#pragma unroll
    for (int q = 0; q < 8; q++) {
        acc[q] = a0[q] + a1[q];
        acc[q] += __shfl_xor_sync(0xFFFFFFFFu, acc[q], 16);
    }

    const float4* b4p = reinterpret_cast<const float4*>(bias);
    float4 bA = __ldg(&b4p[hlane * 2]);
    float4 bB = __ldg(&b4p[hlane * 2 + 1]);
    float bb[8] = {bA.x, bA.y, bA.z, bA.w, bB.x, bB.y, bB.z, bB.w};
    float ax[8];
#pragma unroll
    for (int q = 0; q < 8; q++) ax[q] = acc[q] * di + bb[q];

    // LN: 8 local + xor-reduce over 16 hlanes (values duplicated across halves)
    float s = 0.f;
#pragma unroll
    for (int q = 0; q < 8; q++) s += ax[q];
#pragma unroll
    for (int o = 8; o > 0; o >>= 1) s += __shfl_xor_sync(0xFFFFFFFFu, s, o);
    float mu = s * (1.0f / D);

    float dv[8];
    float sq = 0.f;
#pragma unroll
    for (int q = 0; q < 8; q++) { dv[q] = ax[q] - mu; sq += dv[q] * dv[q]; }
#pragma unroll
    for (int o = 8; o > 0; o >>= 1) sq += __shfl_xor_sync(0xFFFFFFFFu, sq, o);
    float rs = rsqrtf(sq * (1.0f / D) + LN_EPS);

    const float4* g4p = reinterpret_cast<const float4*>(lng);
    const float4* p4p = reinterpret_cast<const float4*>(lnb);
    float4 gA = __ldg(&g4p[hlane * 2]);
    float4 gB = __ldg(&g4p[hlane * 2 + 1]);
    float4 pA = __ldg(&p4p[hlane * 2]);
    float4 pB = __ldg(&p4p[hlane * 2 + 1]);
    float gg[8] = {gA.x, gA.y, gA.z, gA.w, gB.x, gB.y, gB.z, gB.w};
    float pp[8] = {pA.x, pA.y, pA.z, pA.w, pB.x, pB.y, pB.z, pB.w};
#pragma unroll
    for (int q = 0; q < 8; q++)
        outv[q] = fmaxf(dv[q] * rs * gg[q] + pp[q], 0.f);
}

// gather1: writes fp16 rows (lanes 0-15 store 16B each = full 256B row)
__global__ void __launch_bounds__(256) k_gather1(const __half* __restrict__ h,
                                                 const float* __restrict__ bias,
                                                 const float* __restrict__ lng,
                                                 const float* __restrict__ lnb,
                                                 __half* __restrict__ outh) {
    int node = blockIdx.x * 8 + (threadIdx.x >> 5);
    if (node >= N_NODES) return;
    int lane = threadIdx.x & 31;
    float ov[8];
    gather_ln_row8(h, bias, lng, lnb, node, lane, ov);
    if ((lane >> 4) == 0) {
        int hlane = lane & 15;
        __half2 h0 = __floats2half2_rn(ov[0], ov[1]);
        __half2 h1 = __floats2half2_rn(ov[2], ov[3]);
        __half2 h2 = __floats2half2_rn(ov[4], ov[5]);
        __half2 h3 = __floats2half2_rn(ov[6], ov[7]);
        uint4 wv;
        wv.x = *reinterpret_cast<uint32_t*>(&h0);
        wv.y = *reinterpret_cast<uint32_t*>(&h1);
        wv.z = *reinterpret_cast<uint32_t*>(&h2);
        wv.w = *reinterpret_cast<uint32_t*>(&h3);
        reinterpret_cast<uint4*>(outh)[node * 16 + hlane] = wv;
    }
}

// gather2: accumulates into g_pooled/g_gcnt (batch sorted). 12500 blocks, no tail.
__global__ void __launch_bounds__(256) k_gather2_pool(const __half* __restrict__ h,
                                                      const float* __restrict__ bias,
                                                      const float* __restrict__ lng,
                                                      const float* __restrict__ lnb,
                                                      const int* __restrict__ batch) {
    __shared__ float acc[D];
    __shared__ int scnt;
    int tid = threadIdx.x;
    int node = blockIdx.x * 8 + (tid >> 5);
    int lane = tid & 31;

    if (tid < D) acc[tid] = 0.f;
    if (tid == 0) scnt = 0;
    __syncthreads();

    float ov[8];
    gather_ln_row8(h, bias, lng, lnb, node, lane, ov);

    int gFirst = __ldg(&batch[blockIdx.x * 8]);
    int gMine  = __ldg(&batch[node]);
    if ((lane >> 4) == 0) {
        int hlane = lane & 15;
        if (gMine == gFirst) {
#pragma unroll
            for (int q = 0; q < 8; q++) atomicAdd(&acc[hlane * 8 + q], ov[q]);
            if (lane == 0) atomicAdd(&scnt, 1);
        } else {
#pragma unroll
            for (int q = 0; q < 8; q++)
                atomicAdd(&g_pooled[gMine * D + hlane * 8 + q], ov[q]);
            if (lane == 0) atomicAdd(&g_gcnt[gMine], 1.0f);
        }
    }
    __syncthreads();

    if (tid < D) atomicAdd(&g_pooled[gFirst * D + tid], acc[tid]);
    if (tid == 0) atomicAdd(&g_gcnt[gFirst], (float)scnt);
}

// ---------------- head ----------------
__global__ void __launch_bounds__(1024) k_final(const float* __restrict__ lw,
                                                const float* __restrict__ lb,
                                                float* __restrict__ out) {
    int t = threadIdx.x;
    int g = t >> 4;
    int o = t & 15;
    float acc = 0.f;
#pragma unroll 8
    for (int f = 0; f < D; f++) acc += g_pooled[g * D + f] * __ldg(&lw[f * DOUT + o]);
    out[t] = acc / fmaxf(g_gcnt[g], 1.0f) + __ldg(&lb[o]);
}

// ---------------- launch ----------------
extern "C" void kernel_launch(void* const* d_in, const int* in_sizes, int n_in,
                              void* d_out, int out_size) {
    const float* x     = (const float*)d_in[0];
    const int*   ei    = (const int*)d_in[1];
    const int*   src   = ei;
    const int*   dst   = ei + N_EDGES;
    const int*   batch = (const int*)d_in[2];
    const float* W1    = (const float*)d_in[3];
    const float* b1    = (const float*)d_in[4];
    const float* W2    = (const float*)d_in[5];
    const float* b2    = (const float*)d_in[6];
    const float* lng   = (const float*)d_in[7];
    const float* lnb   = (const float*)d_in[8];
    const float* lw    = (const float*)d_in[9];
    const float* lbias = (const float*)d_in[10];
    float* out = (float*)d_out;

    __half* pAh = nullptr;
    float*  pB  = nullptr;
    cudaGetSymbolAddress((void**)&pAh, g_Ah);
    cudaGetSymbolAddress((void**)&pB, g_B);
    __half* pBh = (__half*)pB;

    static cudaStream_t s_side = nullptr;
    static cudaEvent_t  s_evFork = nullptr, s_evG1 = nullptr, s_evJoin = nullptr;
    if (!s_side) {
        cudaStreamCreateWithFlags(&s_side, cudaStreamNonBlocking);
        cudaEventCreateWithFlags(&s_evFork, cudaEventDisableTiming);
        cudaEventCreateWithFlags(&s_evG1, cudaEventDisableTiming);
        cudaEventCreateWithFlags(&s_evJoin, cudaEventDisableTiming);
    }
    cudaStream_t s0 = 0;

    const int T = 256;
    // count (cnti zeroed by previous launch's k_zero / module init)
    k_count<<<(N_EDGES + T - 1) / T, T, 0, s0>>>(dst);

    // fork: side stream builds CSR (+ g_dinv in scan1) while main runs GEMM1
    cudaEventRecord(s_evFork, s0);
    cudaStreamWaitEvent(s_side, s_evFork, 0);
    k_scan1<<<SCAN_NB, SCAN_B, 0, s_side>>>();
    k_scan2<<<1, 128, 0, s_side>>>();
    k_scan3<<<SCAN_NB, SCAN_B, 0, s_side>>>();
    k_fill<<<(N_EDGES + T - 1) / T, T, 0, s_side>>>(src, dst);

    // GEMM1 on main stream (epilogue computes dinv from cnti)
    k_gemm<<<(N_NODES + 127) / 128, 256, 0, s0>>>(x, W1, pAh);
    cudaEventRecord(s_evG1, s0);

    // side: after gemm1's last cnti read, zero cnti/pooled/gcnt
    cudaStreamWaitEvent(s_side, s_evG1, 0);
    k_zero<<<(N_NODES + T - 1) / T, T, 0, s_side>>>();
    cudaEventRecord(s_evJoin, s_side);

    // join: gather1 needs CSR + g_dinv; gather2 needs zeroed pooled/gcnt
    cudaStreamWaitEvent(s0, s_evJoin, 0);
    k_gather1<<<(N_NODES + 7) / 8, 256, 0, s0>>>(pAh, b1, lng, lnb, pBh);

    // layer 2
    k_gemmh<<<(N_NODES + 127) / 128, 256, 0, s0>>>(pBh, W2, pAh);
    k_gather2_pool<<<(N_NODES + 7) / 8, 256, 0, s0>>>(pAh, b2, lng, lnb, batch);

    // head
    k_final<<<1, 1024, 0, s0>>>(lw, lbias, out);
}